// round 1
// baseline (speedup 1.0000x reference)
#include <cuda_runtime.h>
#include <math.h>

#define BATCH   64
#define HEADS   16
#define HDIM    128
#define SLOTS   4096
#define EMB     2048
#define SPLITS  8
#define CHUNK   512      // SLOTS / SPLITS
#define KSPLIT  8
#define NQKV    2304     // 2048 + 128 + 128

// ---------------- scratch (static device memory; no allocations) ----------------
__device__ float g_part_qkv[KSPLIT * BATCH * NQKV];   // split-K partials for qkv
__device__ float g_q[BATCH * EMB];                    // q (pre-scaled at use site)
__device__ float g_kv[BATCH * 256];                   // [b][0:128]=k_new, [128:256]=v_new
__device__ float g_pout[BATCH * SPLITS * HEADS * HDIM];
__device__ float g_pm[BATCH * SPLITS * HEADS];
__device__ float g_pl[BATCH * SPLITS * HEADS];
__device__ float g_attn[BATCH * EMB];                 // attention output, [b][h*128+d]
__device__ float g_part_o[KSPLIT * BATCH * EMB];      // split-K partials for out proj

// =================================================================
// Fused QKV GEMM: out[m][n] over n in [0,2304): Wq | Wk | Wv columns
// grid (36 n-tiles, KSPLIT), 256 threads, 64x64 tile, Kc = 256
// =================================================================
__global__ void gemm_qkv_kernel(const float* __restrict__ x,
                                const float* __restrict__ Wq,
                                const float* __restrict__ Wk,
                                const float* __restrict__ Wv) {
    __shared__ __align__(16) float xT[64][68];
    __shared__ __align__(16) float ws[64][64];

    const int tile = blockIdx.x;
    const int ks   = blockIdx.y;
    const int n0   = tile * 64;
    const float* W; int Nw, col0;
    if (n0 < 2048)      { W = Wq; Nw = 2048; col0 = n0; }
    else if (n0 < 2176) { W = Wk; Nw = 128;  col0 = n0 - 2048; }
    else                { W = Wv; Nw = 128;  col0 = n0 - 2176; }

    const int t  = threadIdx.x;
    const int nl = t & 63;
    const int mg = t >> 6;           // 0..3, 16 rows each

    float acc[16];
#pragma unroll
    for (int i = 0; i < 16; i++) acc[i] = 0.f;

    const int kbase = ks * (EMB / KSPLIT);   // 256-wide K slice

    for (int kk = 0; kk < EMB / KSPLIT; kk += 64) {
        // stage x[64][64] transposed into xT[k][m]
        {
            const int m  = t >> 2;
            const int q4 = (t & 3) * 16;
            const float4* src = (const float4*)(x + (size_t)m * EMB + kbase + kk + q4);
#pragma unroll
            for (int i = 0; i < 4; i++) {
                float4 v = src[i];
                int kb = q4 + i * 4;
                xT[kb + 0][m] = v.x; xT[kb + 1][m] = v.y;
                xT[kb + 2][m] = v.z; xT[kb + 3][m] = v.w;
            }
        }
        // stage W[64][64]
#pragma unroll
        for (int i = 0; i < 4; i++) {
            int f  = t + 256 * i;
            int kr = f >> 4;
            int nc = (f & 15) * 4;
            float4 v = *(const float4*)(W + (size_t)(kbase + kk + kr) * Nw + col0 + nc);
            *(float4*)&ws[kr][nc] = v;
        }
        __syncthreads();

#pragma unroll
        for (int k = 0; k < 64; k++) {
            float w = ws[k][nl];
            const float4* xr = (const float4*)&xT[k][mg * 16];
            float4 a0 = xr[0], a1 = xr[1], a2 = xr[2], a3 = xr[3];
            acc[0]  += a0.x * w; acc[1]  += a0.y * w; acc[2]  += a0.z * w; acc[3]  += a0.w * w;
            acc[4]  += a1.x * w; acc[5]  += a1.y * w; acc[6]  += a1.z * w; acc[7]  += a1.w * w;
            acc[8]  += a2.x * w; acc[9]  += a2.y * w; acc[10] += a2.z * w; acc[11] += a2.w * w;
            acc[12] += a3.x * w; acc[13] += a3.y * w; acc[14] += a3.z * w; acc[15] += a3.w * w;
        }
        __syncthreads();
    }

#pragma unroll
    for (int i = 0; i < 16; i++) {
        int m = mg * 16 + i;
        g_part_qkv[((size_t)ks * BATCH + m) * NQKV + n0 + nl] = acc[i];
    }
}

__global__ void reduce_qkv_kernel(const float* __restrict__ bq,
                                  const float* __restrict__ bk,
                                  const float* __restrict__ bv) {
    int i = blockIdx.x * 256 + threadIdx.x;
    if (i >= BATCH * NQKV) return;
    int b = i / NQKV, j = i - b * NQKV;
    float s = 0.f;
#pragma unroll
    for (int ks = 0; ks < KSPLIT; ks++)
        s += g_part_qkv[((size_t)ks * BATCH + b) * NQKV + j];
    if (j < 2048)      g_q[b * EMB + j] = s + bq[j];
    else if (j < 2176) g_kv[b * 256 + (j - 2048)] = s + bk[j - 2048];
    else               g_kv[b * 256 + 128 + (j - 2176)] = s + bv[j - 2176];
}

// =================================================================
// Flash-decoding attention. grid (SPLITS, BATCH), 256 threads.
// Phase A: scores[16][512] = qs @ K^T (new token substituted at pos)
// exact per-split softmax, Phase B: P @ V -> partials (acc, m, l)
// =================================================================
__global__ void attn_kernel(const float* __restrict__ kc,
                            const float* __restrict__ vc,
                            const int* __restrict__ posa) {
    __shared__ __align__(16) float qs[HEADS][HDIM];
    __shared__ float sc[HEADS][CHUNK + 1];

    const int split = blockIdx.x;
    const int b     = blockIdx.y;
    const int t     = threadIdx.x;
    const int pos   = posa[b];
    const float SCALE = 0.08838834764831845f;   // 1/sqrt(128)

    for (int i = t; i < HEADS * HDIM; i += 256)
        ((float*)qs)[i] = g_q[b * EMB + i] * SCALE;
    __syncthreads();

    const int sbase = split * CHUNK;

    // ---- Phase A: each thread computes 2 K rows x 16 heads ----
    {
        const int s0 = sbase + t;
        const int s1 = sbase + t + 256;
        const float* kr0 = (s0 == pos) ? (g_kv + b * 256)
                                       : (kc + ((size_t)b * SLOTS + s0) * HDIM);
        const float* kr1 = (s1 == pos) ? (g_kv + b * 256)
                                       : (kc + ((size_t)b * SLOTS + s1) * HDIM);
        float acc0[16], acc1[16];
#pragma unroll
        for (int h = 0; h < 16; h++) { acc0[h] = 0.f; acc1[h] = 0.f; }

#pragma unroll 4
        for (int f = 0; f < 32; f++) {
            float4 ka = ((const float4*)kr0)[f];
            float4 kb = ((const float4*)kr1)[f];
#pragma unroll
            for (int h = 0; h < 16; h++) {
                float4 q4 = ((const float4*)qs[h])[f];
                acc0[h] += ka.x * q4.x + ka.y * q4.y + ka.z * q4.z + ka.w * q4.w;
                acc1[h] += kb.x * q4.x + kb.y * q4.y + kb.z * q4.z + kb.w * q4.w;
            }
        }
#pragma unroll
        for (int h = 0; h < 16; h++) {
            sc[h][t]       = acc0[h];
            sc[h][t + 256] = acc1[h];
        }
    }
    __syncthreads();

    // ---- softmax over this split: warp w handles heads 2w, 2w+1 ----
    {
        const int w = t >> 5, lane = t & 31;
#pragma unroll
        for (int hh = 0; hh < 2; hh++) {
            const int h = (w << 1) | hh;
            float m = -1e30f;
            for (int i = lane; i < CHUNK; i += 32) m = fmaxf(m, sc[h][i]);
#pragma unroll
            for (int off = 16; off > 0; off >>= 1)
                m = fmaxf(m, __shfl_xor_sync(0xffffffffu, m, off));
            float l = 0.f;
            for (int i = lane; i < CHUNK; i += 32) {
                float p = __expf(sc[h][i] - m);
                sc[h][i] = p;
                l += p;
            }
#pragma unroll
            for (int off = 16; off > 0; off >>= 1)
                l += __shfl_xor_sync(0xffffffffu, l, off);
            if (lane == 0) {
                g_pm[(b * SPLITS + split) * HEADS + h] = m;
                g_pl[(b * SPLITS + split) * HEADS + h] = l;
            }
        }
    }
    __syncthreads();

    // ---- Phase B: thread (h, dg) accumulates 8 output dims ----
    {
        const int h  = t & 15;
        const int dg = t >> 4;          // 0..15, 8 floats each
        const float* vbase = vc + ((size_t)b * SLOTS + sbase) * HDIM;
        const float* vnew  = g_kv + b * 256 + 128;
        const int pl = pos - sbase;

        float4 oa = make_float4(0.f, 0.f, 0.f, 0.f);
        float4 ob = make_float4(0.f, 0.f, 0.f, 0.f);

#pragma unroll 4
        for (int s = 0; s < CHUNK; s++) {
            float p = sc[h][s];
            const float* vrow = (s == pl) ? vnew : (vbase + (size_t)s * HDIM);
            float4 v0 = ((const float4*)vrow)[dg * 2];
            float4 v1 = ((const float4*)vrow)[dg * 2 + 1];
            oa.x += p * v0.x; oa.y += p * v0.y; oa.z += p * v0.z; oa.w += p * v0.w;
            ob.x += p * v1.x; ob.y += p * v1.y; ob.z += p * v1.z; ob.w += p * v1.w;
        }
        float* dst = g_pout + (((size_t)(b * SPLITS + split) * HEADS + h) * HDIM) + dg * 8;
        ((float4*)dst)[0] = oa;
        ((float4*)dst)[1] = ob;
    }
}

// combine split partials with logsumexp. grid (HEADS, BATCH), 128 threads (d)
__global__ void combine_kernel() {
    const int h = blockIdx.x, b = blockIdx.y, d = threadIdx.x;
    float ms[SPLITS];
    float M = -1e30f;
#pragma unroll
    for (int i = 0; i < SPLITS; i++) {
        ms[i] = g_pm[(b * SPLITS + i) * HEADS + h];
        M = fmaxf(M, ms[i]);
    }
    float Z = 0.f, o = 0.f;
#pragma unroll
    for (int i = 0; i < SPLITS; i++) {
        float e = __expf(ms[i] - M);
        Z += e * g_pl[(b * SPLITS + i) * HEADS + h];
        o += e * g_pout[((size_t)(b * SPLITS + i) * HEADS + h) * HDIM + d];
    }
    g_attn[b * EMB + h * HDIM + d] = o / Z;
}

// =================================================================
// Output projection GEMM: g_attn[64][2048] @ Wo[2048][2048]
// =================================================================
__global__ void gemm_o_kernel(const float* __restrict__ Wo) {
    __shared__ __align__(16) float xT[64][68];
    __shared__ __align__(16) float ws[64][64];

    const int n0 = blockIdx.x * 64;
    const int ks = blockIdx.y;
    const int t  = threadIdx.x;
    const int nl = t & 63;
    const int mg = t >> 6;

    float acc[16];
#pragma unroll
    for (int i = 0; i < 16; i++) acc[i] = 0.f;

    const int kbase = ks * (EMB / KSPLIT);

    for (int kk = 0; kk < EMB / KSPLIT; kk += 64) {
        {
            const int m  = t >> 2;
            const int q4 = (t & 3) * 16;
            const float4* src = (const float4*)(g_attn + (size_t)m * EMB + kbase + kk + q4);
#pragma unroll
            for (int i = 0; i < 4; i++) {
                float4 v = src[i];
                int kb = q4 + i * 4;
                xT[kb + 0][m] = v.x; xT[kb + 1][m] = v.y;
                xT[kb + 2][m] = v.z; xT[kb + 3][m] = v.w;
            }
        }
#pragma unroll
        for (int i = 0; i < 4; i++) {
            int f  = t + 256 * i;
            int kr = f >> 4;
            int nc = (f & 15) * 4;
            float4 v = *(const float4*)(Wo + (size_t)(kbase + kk + kr) * EMB + n0 + nc);
            *(float4*)&ws[kr][nc] = v;
        }
        __syncthreads();

#pragma unroll
        for (int k = 0; k < 64; k++) {
            float w = ws[k][nl];
            const float4* xr = (const float4*)&xT[k][mg * 16];
            float4 a0 = xr[0], a1 = xr[1], a2 = xr[2], a3 = xr[3];
            acc[0]  += a0.x * w; acc[1]  += a0.y * w; acc[2]  += a0.z * w; acc[3]  += a0.w * w;
            acc[4]  += a1.x * w; acc[5]  += a1.y * w; acc[6]  += a1.z * w; acc[7]  += a1.w * w;
            acc[8]  += a2.x * w; acc[9]  += a2.y * w; acc[10] += a2.z * w; acc[11] += a2.w * w;
            acc[12] += a3.x * w; acc[13] += a3.y * w; acc[14] += a3.z * w; acc[15] += a3.w * w;
        }
        __syncthreads();
    }

#pragma unroll
    for (int i = 0; i < 16; i++) {
        int m = mg * 16 + i;
        g_part_o[((size_t)ks * BATCH + m) * EMB + n0 + nl] = acc[i];
    }
}

__global__ void reduce_o_kernel(const float* __restrict__ bo, float* __restrict__ out) {
    int i = blockIdx.x * 256 + threadIdx.x;
    if (i >= BATCH * EMB) return;
    int j = i & (EMB - 1);
    float s = 0.f;
#pragma unroll
    for (int ks = 0; ks < KSPLIT; ks++)
        s += g_part_o[(size_t)ks * BATCH * EMB + i];
    out[i] = s + bo[j];
}

// =================================================================
extern "C" void kernel_launch(void* const* d_in, const int* in_sizes, int n_in,
                              void* d_out, int out_size) {
    const float* x   = (const float*)d_in[0];
    const float* kc  = (const float*)d_in[1];
    const float* vc  = (const float*)d_in[2];
    const int*   pos = (const int*)  d_in[3];
    const float* Wq  = (const float*)d_in[4];
    const float* bq  = (const float*)d_in[5];
    const float* Wk  = (const float*)d_in[6];
    const float* bk  = (const float*)d_in[7];
    const float* Wv  = (const float*)d_in[8];
    const float* bv  = (const float*)d_in[9];
    const float* Wo  = (const float*)d_in[10];
    const float* bo  = (const float*)d_in[11];
    float* out = (float*)d_out;

    gemm_qkv_kernel<<<dim3(NQKV / 64, KSPLIT), 256>>>(x, Wq, Wk, Wv);
    reduce_qkv_kernel<<<(BATCH * NQKV + 255) / 256, 256>>>(bq, bk, bv);
    attn_kernel<<<dim3(SPLITS, BATCH), 256>>>(kc, vc, pos);
    combine_kernel<<<dim3(HEADS, BATCH), 128>>>();
    gemm_o_kernel<<<dim3(EMB / 64, KSPLIT), 256>>>(Wo);
    reduce_o_kernel<<<(BATCH * EMB + 255) / 256, 256>>>(bo, out);
}

// round 4
// speedup vs baseline: 1.3534x; 1.3534x over previous
#include <cuda_runtime.h>
#include <math.h>

#define BATCH   64
#define HEADS   16
#define HDIM    128
#define SLOTS   4096
#define EMB     2048
#define SPLITS  8
#define CHUNK   512      // SLOTS / SPLITS
#define KSPLIT  8
#define NQKV    2304     // 2048 + 128 + 128

typedef unsigned long long u64;

__device__ __forceinline__ u64 pk2(float x, float y) {
    u64 r; asm("mov.b64 %0,{%1,%2};" : "=l"(r) : "f"(x), "f"(y)); return r;
}
__device__ __forceinline__ void fma2(u64& d, u64 a, u64 b) {
    asm("fma.rn.f32x2 %0,%1,%2,%3;" : "=l"(d) : "l"(a), "l"(b), "l"(d));
}
__device__ __forceinline__ float2 up2(u64 a) {
    float lo, hi; asm("mov.b64 {%0,%1},%2;" : "=f"(lo), "=f"(hi) : "l"(a));
    float2 r; r.x = lo; r.y = hi; return r;
}

// ---------------- scratch (static device memory; no allocations) ----------------
__device__ float g_part_qkv[KSPLIT * BATCH * NQKV];
__device__ float g_q[BATCH * EMB];
__device__ float g_kv[BATCH * 256];                   // [b][0:128]=k_new, [128:256]=v_new
__device__ float g_pout[BATCH * SPLITS * HEADS * HDIM];
__device__ float g_pm[BATCH * SPLITS * HEADS];
__device__ float g_pl[BATCH * SPLITS * HEADS];
__device__ float g_attn[BATCH * EMB];
__device__ float g_part_o[KSPLIT * BATCH * EMB];

// =================================================================
// Fused QKV GEMM (f32x2 inner loop)
// =================================================================
__global__ void gemm_qkv_kernel(const float* __restrict__ x,
                                const float* __restrict__ Wq,
                                const float* __restrict__ Wk,
                                const float* __restrict__ Wv) {
    __shared__ __align__(16) float xT[64][68];
    __shared__ __align__(16) float ws[64][64];

    const int n0 = blockIdx.x * 64;
    const int ks = blockIdx.y;
    const float* W; int Nw, col0;
    if (n0 < 2048)      { W = Wq; Nw = 2048; col0 = n0; }
    else if (n0 < 2176) { W = Wk; Nw = 128;  col0 = n0 - 2048; }
    else                { W = Wv; Nw = 128;  col0 = n0 - 2176; }

    const int t  = threadIdx.x;
    const int nl = t & 63;
    const int mg = t >> 6;

    u64 acc2[8];
#pragma unroll
    for (int i = 0; i < 8; i++) acc2[i] = 0ull;

    const int kbase = ks * (EMB / KSPLIT);

    for (int kk = 0; kk < EMB / KSPLIT; kk += 64) {
        {
            const int m  = t >> 2;
            const int q4 = (t & 3) * 16;
            const float4* src = (const float4*)(x + (size_t)m * EMB + kbase + kk + q4);
#pragma unroll
            for (int i = 0; i < 4; i++) {
                float4 v = src[i];
                int kb = q4 + i * 4;
                xT[kb + 0][m] = v.x; xT[kb + 1][m] = v.y;
                xT[kb + 2][m] = v.z; xT[kb + 3][m] = v.w;
            }
        }
#pragma unroll
        for (int i = 0; i < 4; i++) {
            int f  = t + 256 * i;
            int kr = f >> 4;
            int nc = (f & 15) * 4;
            float4 v = *(const float4*)(W + (size_t)(kbase + kk + kr) * Nw + col0 + nc);
            *(float4*)&ws[kr][nc] = v;
        }
        __syncthreads();

#pragma unroll
        for (int k = 0; k < 64; k++) {
            float w = ws[k][nl];
            u64 ww = pk2(w, w);
            const ulonglong2* xr = (const ulonglong2*)&xT[k][mg * 16];
            ulonglong2 p0 = xr[0], p1 = xr[1], p2 = xr[2], p3 = xr[3];
            fma2(acc2[0], p0.x, ww); fma2(acc2[1], p0.y, ww);
            fma2(acc2[2], p1.x, ww); fma2(acc2[3], p1.y, ww);
            fma2(acc2[4], p2.x, ww); fma2(acc2[5], p2.y, ww);
            fma2(acc2[6], p3.x, ww); fma2(acc2[7], p3.y, ww);
        }
        __syncthreads();
    }

#pragma unroll
    for (int i = 0; i < 8; i++) {
        float2 u = up2(acc2[i]);
        int m = mg * 16 + 2 * i;
        g_part_qkv[((size_t)ks * BATCH + m) * NQKV + n0 + nl]     = u.x;
        g_part_qkv[((size_t)ks * BATCH + m + 1) * NQKV + n0 + nl] = u.y;
    }
}

__global__ void reduce_qkv_kernel(const float* __restrict__ bq,
                                  const float* __restrict__ bk,
                                  const float* __restrict__ bv) {
    int i = blockIdx.x * 256 + threadIdx.x;
    if (i >= BATCH * NQKV) return;
    int b = i / NQKV, j = i - b * NQKV;
    float s = 0.f;
#pragma unroll
    for (int ks = 0; ks < KSPLIT; ks++)
        s += g_part_qkv[((size_t)ks * BATCH + b) * NQKV + j];
    if (j < 2048)      g_q[b * EMB + j] = s + bq[j];
    else if (j < 2176) g_kv[b * 256 + (j - 2048)] = s + bk[j - 2048];
    else               g_kv[b * 256 + 128 + (j - 2176)] = s + bv[j - 2176];
}

// =================================================================
// Flash-decoding attention with smem-staged K/V tiles + f32x2.
// grid (SPLITS, BATCH), 256 threads.
// =================================================================
__global__ __launch_bounds__(256, 3)
void attn_kernel(const float* __restrict__ kc,
                 const float* __restrict__ vc,
                 const int* __restrict__ posa) {
    __shared__ __align__(16) float qs[HEADS][132];
    __shared__ __align__(16) float kt[64][132];
    __shared__ __align__(16) float sc[HEADS][CHUNK + 1];

    const int split = blockIdx.x;
    const int b     = blockIdx.y;
    const int t     = threadIdx.x;
    const int pos   = posa[b];
    const float SCALE = 0.08838834764831845f;   // 1/sqrt(128)

    for (int i = t; i < HEADS * HDIM; i += 256)
        qs[i >> 7][i & 127] = g_q[b * EMB + i] * SCALE;

    const int sbase = split * CHUNK;
    const int h = t & 15;
    const int g = t >> 4;            // 0..15

    // ---- Phase A: scores via staged K subtiles (64 rows each) ----
    for (int st = 0; st < 8; st++) {
        __syncthreads();
        const float4* src = (const float4*)(kc + ((size_t)b * SLOTS + sbase + st * 64) * HDIM);
        const float4* knew = (const float4*)(g_kv + b * 256);
#pragma unroll
        for (int j = 0; j < 8; j++) {
            int idx = t + 256 * j;
            int row = idx >> 5, c4 = idx & 31;
            float4 v = (sbase + st * 64 + row == pos) ? knew[c4] : src[row * 32 + c4];
            *(float4*)&kt[row][c4 * 4] = v;
        }
        __syncthreads();

        u64 a0 = 0ull, a1 = 0ull, a2 = 0ull, a3 = 0ull;
#pragma unroll
        for (int f = 0; f < 32; f++) {
            ulonglong2 q2 = ((const ulonglong2*)qs[h])[f];
            ulonglong2 k0 = ((const ulonglong2*)kt[g * 4 + 0])[f];
            ulonglong2 k1 = ((const ulonglong2*)kt[g * 4 + 1])[f];
            ulonglong2 k2 = ((const ulonglong2*)kt[g * 4 + 2])[f];
            ulonglong2 k3 = ((const ulonglong2*)kt[g * 4 + 3])[f];
            fma2(a0, k0.x, q2.x); fma2(a0, k0.y, q2.y);
            fma2(a1, k1.x, q2.x); fma2(a1, k1.y, q2.y);
            fma2(a2, k2.x, q2.x); fma2(a2, k2.y, q2.y);
            fma2(a3, k3.x, q2.x); fma2(a3, k3.y, q2.y);
        }
        float2 u;
        u = up2(a0); sc[h][st * 64 + g * 4 + 0] = u.x + u.y;
        u = up2(a1); sc[h][st * 64 + g * 4 + 1] = u.x + u.y;
        u = up2(a2); sc[h][st * 64 + g * 4 + 2] = u.x + u.y;
        u = up2(a3); sc[h][st * 64 + g * 4 + 3] = u.x + u.y;
    }
    __syncthreads();

    // ---- softmax over this split: warp w handles heads 2w, 2w+1 ----
    {
        const int w = t >> 5, lane = t & 31;
#pragma unroll
        for (int hh = 0; hh < 2; hh++) {
            const int hy = (w << 1) | hh;
            float m = -1e30f;
            for (int i = lane; i < CHUNK; i += 32) m = fmaxf(m, sc[hy][i]);
#pragma unroll
            for (int off = 16; off > 0; off >>= 1)
                m = fmaxf(m, __shfl_xor_sync(0xffffffffu, m, off));
            float l = 0.f;
            for (int i = lane; i < CHUNK; i += 32) {
                float p = __expf(sc[hy][i] - m);
                sc[hy][i] = p;
                l += p;
            }
#pragma unroll
            for (int off = 16; off > 0; off >>= 1)
                l += __shfl_xor_sync(0xffffffffu, l, off);
            if (lane == 0) {
                g_pm[(b * SPLITS + split) * HEADS + hy] = m;
                g_pl[(b * SPLITS + split) * HEADS + hy] = l;
            }
        }
    }

    // ---- Phase B: O accum via staged V subtiles ----
    u64 o0 = 0ull, o1 = 0ull, o2 = 0ull, o3 = 0ull;   // d = g*8 .. g*8+7
    for (int st = 0; st < 8; st++) {
        __syncthreads();
        const float4* src = (const float4*)(vc + ((size_t)b * SLOTS + sbase + st * 64) * HDIM);
        const float4* vnew = (const float4*)(g_kv + b * 256 + 128);
#pragma unroll
        for (int j = 0; j < 8; j++) {
            int idx = t + 256 * j;
            int row = idx >> 5, c4 = idx & 31;
            float4 v = (sbase + st * 64 + row == pos) ? vnew[c4] : src[row * 32 + c4];
            *(float4*)&kt[row][c4 * 4] = v;
        }
        __syncthreads();

#pragma unroll 8
        for (int s = 0; s < 64; s++) {
            float p = sc[h][st * 64 + s];
            u64 pp = pk2(p, p);
            const ulonglong2* vr = (const ulonglong2*)&kt[s][g * 8];
            ulonglong2 v0 = vr[0], v1 = vr[1];
            fma2(o0, v0.x, pp); fma2(o1, v0.y, pp);
            fma2(o2, v1.x, pp); fma2(o3, v1.y, pp);
        }
    }

    float2 u0 = up2(o0), u1 = up2(o1), u2 = up2(o2), u3 = up2(o3);
    float* dst = g_pout + ((size_t)(b * SPLITS + split) * HEADS + h) * HDIM + g * 8;
    float4 r0; r0.x = u0.x; r0.y = u0.y; r0.z = u1.x; r0.w = u1.y;
    float4 r1; r1.x = u2.x; r1.y = u2.y; r1.z = u3.x; r1.w = u3.y;
    ((float4*)dst)[0] = r0;
    ((float4*)dst)[1] = r1;
}

// combine split partials with logsumexp. grid (HEADS, BATCH), 128 threads
__global__ void combine_kernel() {
    const int h = blockIdx.x, b = blockIdx.y, d = threadIdx.x;
    float ms[SPLITS];
    float M = -1e30f;
#pragma unroll
    for (int i = 0; i < SPLITS; i++) {
        ms[i] = g_pm[(b * SPLITS + i) * HEADS + h];
        M = fmaxf(M, ms[i]);
    }
    float Z = 0.f, o = 0.f;
#pragma unroll
    for (int i = 0; i < SPLITS; i++) {
        float e = __expf(ms[i] - M);
        Z += e * g_pl[(b * SPLITS + i) * HEADS + h];
        o += e * g_pout[((size_t)(b * SPLITS + i) * HEADS + h) * HDIM + d];
    }
    g_attn[b * EMB + h * HDIM + d] = o / Z;
}

// =================================================================
// Output projection GEMM (f32x2 inner loop)
// =================================================================
__global__ void gemm_o_kernel(const float* __restrict__ Wo) {
    __shared__ __align__(16) float xT[64][68];
    __shared__ __align__(16) float ws[64][64];

    const int n0 = blockIdx.x * 64;
    const int ks = blockIdx.y;
    const int t  = threadIdx.x;
    const int nl = t & 63;
    const int mg = t >> 6;

    u64 acc2[8];
#pragma unroll
    for (int i = 0; i < 8; i++) acc2[i] = 0ull;

    const int kbase = ks * (EMB / KSPLIT);

    for (int kk = 0; kk < EMB / KSPLIT; kk += 64) {
        {
            const int m  = t >> 2;
            const int q4 = (t & 3) * 16;
            const float4* src = (const float4*)(g_attn + (size_t)m * EMB + kbase + kk + q4);
#pragma unroll
            for (int i = 0; i < 4; i++) {
                float4 v = src[i];
                int kb = q4 + i * 4;
                xT[kb + 0][m] = v.x; xT[kb + 1][m] = v.y;
                xT[kb + 2][m] = v.z; xT[kb + 3][m] = v.w;
            }
        }
#pragma unroll
        for (int i = 0; i < 4; i++) {
            int f  = t + 256 * i;
            int kr = f >> 4;
            int nc = (f & 15) * 4;
            float4 v = *(const float4*)(Wo + (size_t)(kbase + kk + kr) * EMB + n0 + nc);
            *(float4*)&ws[kr][nc] = v;
        }
        __syncthreads();

#pragma unroll
        for (int k = 0; k < 64; k++) {
            float w = ws[k][nl];
            u64 ww = pk2(w, w);
            const ulonglong2* xr = (const ulonglong2*)&xT[k][mg * 16];
            ulonglong2 p0 = xr[0], p1 = xr[1], p2 = xr[2], p3 = xr[3];
            fma2(acc2[0], p0.x, ww); fma2(acc2[1], p0.y, ww);
            fma2(acc2[2], p1.x, ww); fma2(acc2[3], p1.y, ww);
            fma2(acc2[4], p2.x, ww); fma2(acc2[5], p2.y, ww);
            fma2(acc2[6], p3.x, ww); fma2(acc2[7], p3.y, ww);
        }
        __syncthreads();
    }

#pragma unroll
    for (int i = 0; i < 8; i++) {
        float2 u = up2(acc2[i]);
        int m = mg * 16 + 2 * i;
        g_part_o[((size_t)ks * BATCH + m) * EMB + n0 + nl]     = u.x;
        g_part_o[((size_t)ks * BATCH + m + 1) * EMB + n0 + nl] = u.y;
    }
}

__global__ void reduce_o_kernel(const float* __restrict__ bo, float* __restrict__ out) {
    int i = blockIdx.x * 256 + threadIdx.x;
    if (i >= BATCH * EMB) return;
    int j = i & (EMB - 1);
    float s = 0.f;
#pragma unroll
    for (int ks = 0; ks < KSPLIT; ks++)
        s += g_part_o[(size_t)ks * BATCH * EMB + i];
    out[i] = s + bo[j];
}

// =================================================================
extern "C" void kernel_launch(void* const* d_in, const int* in_sizes, int n_in,
                              void* d_out, int out_size) {
    const float* x   = (const float*)d_in[0];
    const float* kc  = (const float*)d_in[1];
    const float* vc  = (const float*)d_in[2];
    const int*   pos = (const int*)  d_in[3];
    const float* Wq  = (const float*)d_in[4];
    const float* bq  = (const float*)d_in[5];
    const float* Wk  = (const float*)d_in[6];
    const float* bk  = (const float*)d_in[7];
    const float* Wv  = (const float*)d_in[8];
    const float* bv  = (const float*)d_in[9];
    const float* Wo  = (const float*)d_in[10];
    const float* bo  = (const float*)d_in[11];
    float* out = (float*)d_out;

    gemm_qkv_kernel<<<dim3(NQKV / 64, KSPLIT), 256>>>(x, Wq, Wk, Wv);
    reduce_qkv_kernel<<<(BATCH * NQKV + 255) / 256, 256>>>(bq, bk, bv);
    attn_kernel<<<dim3(SPLITS, BATCH), 256>>>(kc, vc, pos);
    combine_kernel<<<dim3(HEADS, BATCH), 128>>>();
    gemm_o_kernel<<<dim3(EMB / 64, KSPLIT), 256>>>(Wo);
    reduce_o_kernel<<<(BATCH * EMB + 255) / 256, 256>>>(bo, out);
}

// round 5
// speedup vs baseline: 1.6106x; 1.1901x over previous
#include <cuda_runtime.h>
#include <math.h>

#define BATCH   64
#define HEADS   16
#define HDIM    128
#define SLOTS   4096
#define EMB     2048
#define SPLITS  8
#define CHUNK   512      // SLOTS / SPLITS
#define KSPLIT  8
#define NQKV    2304     // 2048 + 128 + 128

typedef unsigned long long u64;

__device__ __forceinline__ u64 pk2(float x, float y) {
    u64 r; asm("mov.b64 %0,{%1,%2};" : "=l"(r) : "f"(x), "f"(y)); return r;
}
__device__ __forceinline__ void fma2(u64& d, u64 a, u64 b) {
    asm("fma.rn.f32x2 %0,%1,%2,%3;" : "=l"(d) : "l"(a), "l"(b), "l"(d));
}
__device__ __forceinline__ float2 up2(u64 a) {
    float lo, hi; asm("mov.b64 {%0,%1},%2;" : "=f"(lo), "=f"(hi) : "l"(a));
    float2 r; r.x = lo; r.y = hi; return r;
}

// ---------------- scratch (static device memory; no allocations) ----------------
__device__ float g_part_qkv[KSPLIT * BATCH * NQKV];
__device__ float g_q[BATCH * EMB];
__device__ float g_kv[BATCH * 256];                   // [b][0:128]=k_new, [128:256]=v_new
__device__ float g_pout[BATCH * SPLITS * HEADS * HDIM];
__device__ float g_pm[BATCH * SPLITS * HEADS];
__device__ float g_pl[BATCH * SPLITS * HEADS];
__device__ float g_attn[BATCH * EMB];
__device__ float g_part_o[KSPLIT * BATCH * EMB];

// =================================================================
// Fused QKV GEMM (f32x2 inner loop, register double-buffered loads)
// =================================================================
__global__ void gemm_qkv_kernel(const float* __restrict__ x,
                                const float* __restrict__ Wq,
                                const float* __restrict__ Wk,
                                const float* __restrict__ Wv) {
    __shared__ __align__(16) float xT[64][68];
    __shared__ __align__(16) float ws[64][64];

    const int n0 = blockIdx.x * 64;
    const int ks = blockIdx.y;
    const float* W; int Nw, col0;
    if (n0 < 2048)      { W = Wq; Nw = 2048; col0 = n0; }
    else if (n0 < 2176) { W = Wk; Nw = 128;  col0 = n0 - 2048; }
    else                { W = Wv; Nw = 128;  col0 = n0 - 2176; }

    const int t  = threadIdx.x;
    const int nl = t & 63;
    const int mg = t >> 6;
    const int mrow = t >> 2;
    const int q4   = (t & 3) * 16;

    u64 acc2[8];
#pragma unroll
    for (int i = 0; i < 8; i++) acc2[i] = 0ull;

    const int kbase = ks * (EMB / KSPLIT);

    float4 rx[4], rw[4];
    // prologue loads for kk = 0
    {
        const float4* src = (const float4*)(x + (size_t)mrow * EMB + kbase + q4);
#pragma unroll
        for (int i = 0; i < 4; i++) rx[i] = src[i];
#pragma unroll
        for (int i = 0; i < 4; i++) {
            int f = t + 256 * i; int kr = f >> 4; int nc = (f & 15) * 4;
            rw[i] = *(const float4*)(W + (size_t)(kbase + kr) * Nw + col0 + nc);
        }
    }

    for (int kk = 0; kk < EMB / KSPLIT; kk += 64) {
        // commit staged registers to smem
#pragma unroll
        for (int i = 0; i < 4; i++) {
            int kb = q4 + i * 4;
            xT[kb + 0][mrow] = rx[i].x; xT[kb + 1][mrow] = rx[i].y;
            xT[kb + 2][mrow] = rx[i].z; xT[kb + 3][mrow] = rx[i].w;
        }
#pragma unroll
        for (int i = 0; i < 4; i++) {
            int f = t + 256 * i; int kr = f >> 4; int nc = (f & 15) * 4;
            *(float4*)&ws[kr][nc] = rw[i];
        }
        __syncthreads();

        // prefetch next k-slice while computing
        if (kk + 64 < EMB / KSPLIT) {
            const float4* src = (const float4*)(x + (size_t)mrow * EMB + kbase + kk + 64 + q4);
#pragma unroll
            for (int i = 0; i < 4; i++) rx[i] = src[i];
#pragma unroll
            for (int i = 0; i < 4; i++) {
                int f = t + 256 * i; int kr = f >> 4; int nc = (f & 15) * 4;
                rw[i] = *(const float4*)(W + (size_t)(kbase + kk + 64 + kr) * Nw + col0 + nc);
            }
        }

#pragma unroll
        for (int k = 0; k < 64; k++) {
            float w = ws[k][nl];
            u64 ww = pk2(w, w);
            const ulonglong2* xr = (const ulonglong2*)&xT[k][mg * 16];
            ulonglong2 p0 = xr[0], p1 = xr[1], p2 = xr[2], p3 = xr[3];
            fma2(acc2[0], p0.x, ww); fma2(acc2[1], p0.y, ww);
            fma2(acc2[2], p1.x, ww); fma2(acc2[3], p1.y, ww);
            fma2(acc2[4], p2.x, ww); fma2(acc2[5], p2.y, ww);
            fma2(acc2[6], p3.x, ww); fma2(acc2[7], p3.y, ww);
        }
        __syncthreads();
    }

#pragma unroll
    for (int i = 0; i < 8; i++) {
        float2 u = up2(acc2[i]);
        int m = mg * 16 + 2 * i;
        g_part_qkv[((size_t)ks * BATCH + m) * NQKV + n0 + nl]     = u.x;
        g_part_qkv[((size_t)ks * BATCH + m + 1) * NQKV + n0 + nl] = u.y;
    }
}

__global__ void reduce_qkv_kernel(const float* __restrict__ bq,
                                  const float* __restrict__ bk,
                                  const float* __restrict__ bv) {
    int i = blockIdx.x * 256 + threadIdx.x;
    if (i >= BATCH * NQKV) return;
    int b = i / NQKV, j = i - b * NQKV;
    float s = 0.f;
#pragma unroll
    for (int ks = 0; ks < KSPLIT; ks++)
        s += g_part_qkv[((size_t)ks * BATCH + b) * NQKV + j];
    if (j < 2048)      g_q[b * EMB + j] = s + bq[j];
    else if (j < 2176) g_kv[b * 256 + (j - 2048)] = s + bk[j - 2048];
    else               g_kv[b * 256 + 128 + (j - 2176)] = s + bv[j - 2176];
}

// =================================================================
// Flash-decoding attention: cp.async double-buffered K/V staging.
// grid (SPLITS, BATCH), 256 threads, dynamic smem (~107KB, 2 blocks/SM)
// =================================================================
struct AttnSmem {
    float kt[2][64][128];   // K/V staging buffers (no pad: compute reads are broadcast)
    float qs[HEADS][132];   // padded: conflict-free across h
    float sc[HEADS][CHUNK + 1];
};

__device__ __forceinline__ void stage_tile(const float* __restrict__ cache,
                                           const float* __restrict__ kvnew,
                                           float* __restrict__ dst,
                                           int b, int srow0, int pos, int t) {
    const float* base = cache + ((size_t)b * SLOTS + srow0) * HDIM;
#pragma unroll
    for (int j = 0; j < 8; j++) {
        int idx = t + 256 * j;
        int row = idx >> 5, c4 = idx & 31;
        const float* src = (srow0 + row == pos) ? (kvnew + c4 * 4)
                                                : (base + (size_t)row * HDIM + c4 * 4);
        unsigned d = (unsigned)__cvta_generic_to_shared(dst + row * 128 + c4 * 4);
        asm volatile("cp.async.cg.shared.global [%0],[%1],16;" :: "r"(d), "l"(src));
    }
    asm volatile("cp.async.commit_group;");
}

__global__ __launch_bounds__(256, 2)
void attn_kernel(const float* __restrict__ kc,
                 const float* __restrict__ vc,
                 const int* __restrict__ posa) {
    extern __shared__ __align__(16) char sraw[];
    AttnSmem& S = *reinterpret_cast<AttnSmem*>(sraw);

    const int split = blockIdx.x;
    const int b     = blockIdx.y;
    const int t     = threadIdx.x;
    const int pos   = posa[b];
    const float SCALE = 0.08838834764831845f;   // 1/sqrt(128)

    for (int i = t; i < HEADS * HDIM; i += 256)
        S.qs[i >> 7][i & 127] = g_q[b * EMB + i] * SCALE;

    const int sbase = split * CHUNK;
    const int h = t & 15;
    const int g = t >> 4;            // 0..15
    const float* knew = g_kv + b * 256;
    const float* vnew = g_kv + b * 256 + 128;

    // ---- Phase A: scores, pipelined K subtiles ----
    stage_tile(kc, knew, &S.kt[0][0][0], b, sbase, pos, t);
    for (int st = 0; st < 8; st++) {
        if (st < 7) stage_tile(kc, knew, &S.kt[(st + 1) & 1][0][0], b, sbase + (st + 1) * 64, pos, t);
        else        stage_tile(vc, vnew, &S.kt[0][0][0],            b, sbase,                pos, t);
        asm volatile("cp.async.wait_group 1;");
        __syncthreads();

        const float (*kcur)[128] = S.kt[st & 1];
        u64 a0 = 0ull, a1 = 0ull, a2 = 0ull, a3 = 0ull;
#pragma unroll
        for (int f = 0; f < 32; f++) {
            ulonglong2 q2 = ((const ulonglong2*)S.qs[h])[f];
            ulonglong2 k0 = ((const ulonglong2*)kcur[g * 4 + 0])[f];
            ulonglong2 k1 = ((const ulonglong2*)kcur[g * 4 + 1])[f];
            ulonglong2 k2 = ((const ulonglong2*)kcur[g * 4 + 2])[f];
            ulonglong2 k3 = ((const ulonglong2*)kcur[g * 4 + 3])[f];
            fma2(a0, k0.x, q2.x); fma2(a0, k0.y, q2.y);
            fma2(a1, k1.x, q2.x); fma2(a1, k1.y, q2.y);
            fma2(a2, k2.x, q2.x); fma2(a2, k2.y, q2.y);
            fma2(a3, k3.x, q2.x); fma2(a3, k3.y, q2.y);
        }
        float2 u;
        u = up2(a0); S.sc[h][st * 64 + g * 4 + 0] = u.x + u.y;
        u = up2(a1); S.sc[h][st * 64 + g * 4 + 1] = u.x + u.y;
        u = up2(a2); S.sc[h][st * 64 + g * 4 + 2] = u.x + u.y;
        u = up2(a3); S.sc[h][st * 64 + g * 4 + 3] = u.x + u.y;
        __syncthreads();
    }

    // ---- softmax (V0 load in flight; V1 issued in Phase B iter 0) ----
    {
        const int w = t >> 5, lane = t & 31;
#pragma unroll
        for (int hh = 0; hh < 2; hh++) {
            const int hy = (w << 1) | hh;
            float m = -1e30f;
            for (int i = lane; i < CHUNK; i += 32) m = fmaxf(m, S.sc[hy][i]);
#pragma unroll
            for (int off = 16; off > 0; off >>= 1)
                m = fmaxf(m, __shfl_xor_sync(0xffffffffu, m, off));
            float l = 0.f;
            for (int i = lane; i < CHUNK; i += 32) {
                float p = __expf(S.sc[hy][i] - m);
                S.sc[hy][i] = p;
                l += p;
            }
#pragma unroll
            for (int off = 16; off > 0; off >>= 1)
                l += __shfl_xor_sync(0xffffffffu, l, off);
            if (lane == 0) {
                g_pm[(b * SPLITS + split) * HEADS + hy] = m;
                g_pl[(b * SPLITS + split) * HEADS + hy] = l;
            }
        }
    }

    // ---- Phase B: O accum, pipelined V subtiles ----
    u64 o0 = 0ull, o1 = 0ull, o2 = 0ull, o3 = 0ull;   // d = g*8 .. g*8+7
    for (int st = 0; st < 8; st++) {
        if (st < 7) {
            stage_tile(vc, vnew, &S.kt[(st + 1) & 1][0][0], b, sbase + (st + 1) * 64, pos, t);
            asm volatile("cp.async.wait_group 1;");
        } else {
            asm volatile("cp.async.wait_group 0;");
        }
        __syncthreads();

        const float (*vcur)[128] = S.kt[st & 1];
#pragma unroll 8
        for (int s = 0; s < 64; s++) {
            float p = S.sc[h][st * 64 + s];
            u64 pp = pk2(p, p);
            const ulonglong2* vr = (const ulonglong2*)&vcur[s][g * 8];
            ulonglong2 v0 = vr[0], v1 = vr[1];
            fma2(o0, v0.x, pp); fma2(o1, v0.y, pp);
            fma2(o2, v1.x, pp); fma2(o3, v1.y, pp);
        }
        __syncthreads();
    }

    float2 u0 = up2(o0), u1 = up2(o1), u2 = up2(o2), u3 = up2(o3);
    float* dst = g_pout + ((size_t)(b * SPLITS + split) * HEADS + h) * HDIM + g * 8;
    float4 r0; r0.x = u0.x; r0.y = u0.y; r0.z = u1.x; r0.w = u1.y;
    float4 r1; r1.x = u2.x; r1.y = u2.y; r1.z = u3.x; r1.w = u3.y;
    ((float4*)dst)[0] = r0;
    ((float4*)dst)[1] = r1;
}

// combine split partials with logsumexp. grid (HEADS, BATCH), 128 threads
__global__ void combine_kernel() {
    const int h = blockIdx.x, b = blockIdx.y, d = threadIdx.x;
    float ms[SPLITS];
    float M = -1e30f;
#pragma unroll
    for (int i = 0; i < SPLITS; i++) {
        ms[i] = g_pm[(b * SPLITS + i) * HEADS + h];
        M = fmaxf(M, ms[i]);
    }
    float Z = 0.f, o = 0.f;
#pragma unroll
    for (int i = 0; i < SPLITS; i++) {
        float e = __expf(ms[i] - M);
        Z += e * g_pl[(b * SPLITS + i) * HEADS + h];
        o += e * g_pout[((size_t)(b * SPLITS + i) * HEADS + h) * HDIM + d];
    }
    g_attn[b * EMB + h * HDIM + d] = o / Z;
}

// =================================================================
// Output projection GEMM (f32x2, register double-buffered loads)
// =================================================================
__global__ void gemm_o_kernel(const float* __restrict__ Wo) {
    __shared__ __align__(16) float xT[64][68];
    __shared__ __align__(16) float ws[64][64];

    const int n0 = blockIdx.x * 64;
    const int ks = blockIdx.y;
    const int t  = threadIdx.x;
    const int nl = t & 63;
    const int mg = t >> 6;
    const int mrow = t >> 2;
    const int q4   = (t & 3) * 16;

    u64 acc2[8];
#pragma unroll
    for (int i = 0; i < 8; i++) acc2[i] = 0ull;

    const int kbase = ks * (EMB / KSPLIT);

    float4 rx[4], rw[4];
    {
        const float4* src = (const float4*)(g_attn + (size_t)mrow * EMB + kbase + q4);
#pragma unroll
        for (int i = 0; i < 4; i++) rx[i] = src[i];
#pragma unroll
        for (int i = 0; i < 4; i++) {
            int f = t + 256 * i; int kr = f >> 4; int nc = (f & 15) * 4;
            rw[i] = *(const float4*)(Wo + (size_t)(kbase + kr) * EMB + n0 + nc);
        }
    }

    for (int kk = 0; kk < EMB / KSPLIT; kk += 64) {
#pragma unroll
        for (int i = 0; i < 4; i++) {
            int kb = q4 + i * 4;
            xT[kb + 0][mrow] = rx[i].x; xT[kb + 1][mrow] = rx[i].y;
            xT[kb + 2][mrow] = rx[i].z; xT[kb + 3][mrow] = rx[i].w;
        }
#pragma unroll
        for (int i = 0; i < 4; i++) {
            int f = t + 256 * i; int kr = f >> 4; int nc = (f & 15) * 4;
            *(float4*)&ws[kr][nc] = rw[i];
        }
        __syncthreads();

        if (kk + 64 < EMB / KSPLIT) {
            const float4* src = (const float4*)(g_attn + (size_t)mrow * EMB + kbase + kk + 64 + q4);
#pragma unroll
            for (int i = 0; i < 4; i++) rx[i] = src[i];
#pragma unroll
            for (int i = 0; i < 4; i++) {
                int f = t + 256 * i; int kr = f >> 4; int nc = (f & 15) * 4;
                rw[i] = *(const float4*)(Wo + (size_t)(kbase + kk + 64 + kr) * EMB + n0 + nc);
            }
        }

#pragma unroll
        for (int k = 0; k < 64; k++) {
            float w = ws[k][nl];
            u64 ww = pk2(w, w);
            const ulonglong2* xr = (const ulonglong2*)&xT[k][mg * 16];
            ulonglong2 p0 = xr[0], p1 = xr[1], p2 = xr[2], p3 = xr[3];
            fma2(acc2[0], p0.x, ww); fma2(acc2[1], p0.y, ww);
            fma2(acc2[2], p1.x, ww); fma2(acc2[3], p1.y, ww);
            fma2(acc2[4], p2.x, ww); fma2(acc2[5], p2.y, ww);
            fma2(acc2[6], p3.x, ww); fma2(acc2[7], p3.y, ww);
        }
        __syncthreads();
    }

#pragma unroll
    for (int i = 0; i < 8; i++) {
        float2 u = up2(acc2[i]);
        int m = mg * 16 + 2 * i;
        g_part_o[((size_t)ks * BATCH + m) * EMB + n0 + nl]     = u.x;
        g_part_o[((size_t)ks * BATCH + m + 1) * EMB + n0 + nl] = u.y;
    }
}

__global__ void reduce_o_kernel(const float* __restrict__ bo, float* __restrict__ out) {
    int i = blockIdx.x * 256 + threadIdx.x;
    if (i >= BATCH * EMB) return;
    int j = i & (EMB - 1);
    float s = 0.f;
#pragma unroll
    for (int ks = 0; ks < KSPLIT; ks++)
        s += g_part_o[(size_t)ks * BATCH * EMB + i];
    out[i] = s + bo[j];
}

// =================================================================
extern "C" void kernel_launch(void* const* d_in, const int* in_sizes, int n_in,
                              void* d_out, int out_size) {
    const float* x   = (const float*)d_in[0];
    const float* kc  = (const float*)d_in[1];
    const float* vc  = (const float*)d_in[2];
    const int*   pos = (const int*)  d_in[3];
    const float* Wq  = (const float*)d_in[4];
    const float* bq  = (const float*)d_in[5];
    const float* Wk  = (const float*)d_in[6];
    const float* bk  = (const float*)d_in[7];
    const float* Wv  = (const float*)d_in[8];
    const float* bv  = (const float*)d_in[9];
    const float* Wo  = (const float*)d_in[10];
    const float* bo  = (const float*)d_in[11];
    float* out = (float*)d_out;

    cudaFuncSetAttribute(attn_kernel, cudaFuncAttributeMaxDynamicSharedMemorySize,
                         (int)sizeof(AttnSmem));

    gemm_qkv_kernel<<<dim3(NQKV / 64, KSPLIT), 256>>>(x, Wq, Wk, Wv);
    reduce_qkv_kernel<<<(BATCH * NQKV + 255) / 256, 256>>>(bq, bk, bv);
    attn_kernel<<<dim3(SPLITS, BATCH), 256, sizeof(AttnSmem)>>>(kc, vc, pos);
    combine_kernel<<<dim3(HEADS, BATCH), 128>>>();
    gemm_o_kernel<<<dim3(EMB / 64, KSPLIT), 256>>>(Wo);
    reduce_o_kernel<<<(BATCH * EMB + 255) / 256, 256>>>(bo, out);
}

// round 6
// speedup vs baseline: 1.8806x; 1.1676x over previous
#include <cuda_runtime.h>
#include <math.h>

#define BATCH   64
#define HEADS   16
#define HDIM    128
#define SLOTS   4096
#define EMB     2048
#define SPLITS  8
#define CHUNK   512      // SLOTS / SPLITS
#define KSPLIT  8
#define NQKV    2304     // 2048 + 128 + 128

typedef unsigned long long u64;

__device__ __forceinline__ u64 pk2(float x, float y) {
    u64 r; asm("mov.b64 %0,{%1,%2};" : "=l"(r) : "f"(x), "f"(y)); return r;
}
__device__ __forceinline__ void fma2(u64& d, u64 a, u64 b) {
    asm("fma.rn.f32x2 %0,%1,%2,%3;" : "=l"(d) : "l"(a), "l"(b), "l"(d));
}
__device__ __forceinline__ float2 up2(u64 a) {
    float lo, hi; asm("mov.b64 {%0,%1},%2;" : "=f"(lo), "=f"(hi) : "l"(a));
    float2 r; r.x = lo; r.y = hi; return r;
}
__device__ __forceinline__ float hsum2(u64 a) { float2 u = up2(a); return u.x + u.y; }

// ---------------- scratch (static device memory; no allocations) ----------------
__device__ float g_part_qkv[KSPLIT * BATCH * NQKV];
__device__ float g_q[BATCH * EMB];                    // pre-scaled by 1/sqrt(d)
__device__ float g_kv[BATCH * 256];                   // [b][0:128]=k_new, [128:256]=v_new
__device__ float g_pout[BATCH * SPLITS * HEADS * HDIM];
__device__ float g_pm[BATCH * SPLITS * HEADS];
__device__ float g_pl[BATCH * SPLITS * HEADS];
__device__ float g_attn[BATCH * EMB];
__device__ float g_part_o[KSPLIT * BATCH * EMB];

// =================================================================
// Fused QKV GEMM (f32x2 inner loop, register double-buffered loads)
// =================================================================
__global__ void gemm_qkv_kernel(const float* __restrict__ x,
                                const float* __restrict__ Wq,
                                const float* __restrict__ Wk,
                                const float* __restrict__ Wv) {
    __shared__ __align__(16) float xT[64][68];
    __shared__ __align__(16) float ws[64][64];

    const int n0 = blockIdx.x * 64;
    const int ks = blockIdx.y;
    const float* W; int Nw, col0;
    if (n0 < 2048)      { W = Wq; Nw = 2048; col0 = n0; }
    else if (n0 < 2176) { W = Wk; Nw = 128;  col0 = n0 - 2048; }
    else                { W = Wv; Nw = 128;  col0 = n0 - 2176; }

    const int t  = threadIdx.x;
    const int nl = t & 63;
    const int mg = t >> 6;
    const int mrow = t >> 2;
    const int q4   = (t & 3) * 16;

    u64 acc2[8];
#pragma unroll
    for (int i = 0; i < 8; i++) acc2[i] = 0ull;

    const int kbase = ks * (EMB / KSPLIT);

    float4 rx[4], rw[4];
    {
        const float4* src = (const float4*)(x + (size_t)mrow * EMB + kbase + q4);
#pragma unroll
        for (int i = 0; i < 4; i++) rx[i] = src[i];
#pragma unroll
        for (int i = 0; i < 4; i++) {
            int f = t + 256 * i; int kr = f >> 4; int nc = (f & 15) * 4;
            rw[i] = *(const float4*)(W + (size_t)(kbase + kr) * Nw + col0 + nc);
        }
    }

    for (int kk = 0; kk < EMB / KSPLIT; kk += 64) {
#pragma unroll
        for (int i = 0; i < 4; i++) {
            int kb = q4 + i * 4;
            xT[kb + 0][mrow] = rx[i].x; xT[kb + 1][mrow] = rx[i].y;
            xT[kb + 2][mrow] = rx[i].z; xT[kb + 3][mrow] = rx[i].w;
        }
#pragma unroll
        for (int i = 0; i < 4; i++) {
            int f = t + 256 * i; int kr = f >> 4; int nc = (f & 15) * 4;
            *(float4*)&ws[kr][nc] = rw[i];
        }
        __syncthreads();

        if (kk + 64 < EMB / KSPLIT) {
            const float4* src = (const float4*)(x + (size_t)mrow * EMB + kbase + kk + 64 + q4);
#pragma unroll
            for (int i = 0; i < 4; i++) rx[i] = src[i];
#pragma unroll
            for (int i = 0; i < 4; i++) {
                int f = t + 256 * i; int kr = f >> 4; int nc = (f & 15) * 4;
                rw[i] = *(const float4*)(W + (size_t)(kbase + kk + 64 + kr) * Nw + col0 + nc);
            }
        }

#pragma unroll
        for (int k = 0; k < 64; k++) {
            float w = ws[k][nl];
            u64 ww = pk2(w, w);
            const ulonglong2* xr = (const ulonglong2*)&xT[k][mg * 16];
            ulonglong2 p0 = xr[0], p1 = xr[1], p2 = xr[2], p3 = xr[3];
            fma2(acc2[0], p0.x, ww); fma2(acc2[1], p0.y, ww);
            fma2(acc2[2], p1.x, ww); fma2(acc2[3], p1.y, ww);
            fma2(acc2[4], p2.x, ww); fma2(acc2[5], p2.y, ww);
            fma2(acc2[6], p3.x, ww); fma2(acc2[7], p3.y, ww);
        }
        __syncthreads();
    }

#pragma unroll
    for (int i = 0; i < 8; i++) {
        float2 u = up2(acc2[i]);
        int m = mg * 16 + 2 * i;
        g_part_qkv[((size_t)ks * BATCH + m) * NQKV + n0 + nl]     = u.x;
        g_part_qkv[((size_t)ks * BATCH + m + 1) * NQKV + n0 + nl] = u.y;
    }
}

__global__ void reduce_qkv_kernel(const float* __restrict__ bq,
                                  const float* __restrict__ bk,
                                  const float* __restrict__ bv) {
    int i = blockIdx.x * 256 + threadIdx.x;
    if (i >= BATCH * NQKV) return;
    int b = i / NQKV, j = i - b * NQKV;
    float s = 0.f;
#pragma unroll
    for (int ks = 0; ks < KSPLIT; ks++)
        s += g_part_qkv[((size_t)ks * BATCH + b) * NQKV + j];
    const float SCALE = 0.08838834764831845f;   // 1/sqrt(128)
    if (j < 2048)      g_q[b * EMB + j] = (s + bq[j]) * SCALE;
    else if (j < 2176) g_kv[b * 256 + (j - 2048)] = s + bk[j - 2048];
    else               g_kv[b * 256 + 128 + (j - 2176)] = s + bv[j - 2176];
}

// =================================================================
// Flash-decoding attention: cp.async double-buffered K/V staging,
// register-blocked 2 heads x 4 rows (QK) / 2 heads x 8 dims (PV),
// all smem accesses 1-phase. grid (SPLITS, BATCH), 128 threads.
// =================================================================
#define KTP 132    // kt/qs row stride (floats): banks 4*i, conflict-free
#define SCP 18     // scT row stride: 8B-aligned head pairs

struct AttnSmem {
    float kt[2][64][KTP];        // K/V staging
    float qs[HEADS][KTP];        // q rows
    float scT[CHUNK][SCP];       // scores transposed: [s][2*h2]=h2, [2*h2+1]=h2+8
};

__device__ __forceinline__ void stage_tile(const float* __restrict__ cache,
                                           const float* __restrict__ kvnew,
                                           float* __restrict__ dst,
                                           int b, int srow0, int pos, int t) {
    const float* base = cache + ((size_t)b * SLOTS + srow0) * HDIM;
#pragma unroll
    for (int j = 0; j < 16; j++) {
        int idx = t + 128 * j;
        int row = idx >> 5, c4 = idx & 31;
        const float* src = (srow0 + row == pos) ? (kvnew + c4 * 4)
                                                : (base + (size_t)row * HDIM + c4 * 4);
        unsigned d = (unsigned)__cvta_generic_to_shared(dst + row * KTP + c4 * 4);
        asm volatile("cp.async.cg.shared.global [%0],[%1],16;" :: "r"(d), "l"(src));
    }
    asm volatile("cp.async.commit_group;");
}

__global__ __launch_bounds__(128, 2)
void attn_kernel(const float* __restrict__ kc,
                 const float* __restrict__ vc,
                 const int* __restrict__ posa) {
    extern __shared__ __align__(16) char sraw[];
    AttnSmem& S = *reinterpret_cast<AttnSmem*>(sraw);

    const int split = blockIdx.x;
    const int b     = blockIdx.y;
    const int t     = threadIdx.x;
    const int pos   = posa[b];

    // load q (pre-scaled) into smem
#pragma unroll
    for (int j = 0; j < 16; j++) {
        int i = t + 128 * j;
        S.qs[i >> 7][i & 127] = g_q[b * EMB + i];
    }

    const int sbase = split * CHUNK;
    const int h2 = t & 7;            // heads h2 and h2+8
    const int rg = t >> 3;           // 0..15
    const float* knew = g_kv + b * 256;
    const float* vnew = g_kv + b * 256 + 128;

    // ---- Phase A: scores, pipelined K subtiles (64 rows each) ----
    stage_tile(kc, knew, &S.kt[0][0][0], b, sbase, pos, t);
    for (int st = 0; st < 8; st++) {
        if (st < 7) stage_tile(kc, knew, &S.kt[(st + 1) & 1][0][0], b, sbase + (st + 1) * 64, pos, t);
        else        stage_tile(vc, vnew, &S.kt[0][0][0],            b, sbase,                pos, t);
        asm volatile("cp.async.wait_group 1;");
        __syncthreads();

        const float (*kcur)[KTP] = S.kt[st & 1];
        const float* qa_p = S.qs[h2];
        const float* qb_p = S.qs[h2 + 8];
        const float* k0_p = kcur[rg];
        const float* k1_p = kcur[rg + 16];
        const float* k2_p = kcur[rg + 32];
        const float* k3_p = kcur[rg + 48];

        u64 a00 = 0ull, a01 = 0ull, a02 = 0ull, a03 = 0ull;
        u64 a10 = 0ull, a11 = 0ull, a12 = 0ull, a13 = 0ull;
#pragma unroll 8
        for (int f = 0; f < 32; f++) {
            ulonglong2 qa = *(const ulonglong2*)(qa_p + f * 4);
            ulonglong2 qb = *(const ulonglong2*)(qb_p + f * 4);
            ulonglong2 k0 = *(const ulonglong2*)(k0_p + f * 4);
            ulonglong2 k1 = *(const ulonglong2*)(k1_p + f * 4);
            ulonglong2 k2 = *(const ulonglong2*)(k2_p + f * 4);
            ulonglong2 k3 = *(const ulonglong2*)(k3_p + f * 4);
            fma2(a00, k0.x, qa.x); fma2(a00, k0.y, qa.y);
            fma2(a01, k1.x, qa.x); fma2(a01, k1.y, qa.y);
            fma2(a02, k2.x, qa.x); fma2(a02, k2.y, qa.y);
            fma2(a03, k3.x, qa.x); fma2(a03, k3.y, qa.y);
            fma2(a10, k0.x, qb.x); fma2(a10, k0.y, qb.y);
            fma2(a11, k1.x, qb.x); fma2(a11, k1.y, qb.y);
            fma2(a12, k2.x, qb.x); fma2(a12, k2.y, qb.y);
            fma2(a13, k3.x, qb.x); fma2(a13, k3.y, qb.y);
        }
        int r0 = st * 64 + rg;
        S.scT[r0     ][2 * h2]     = hsum2(a00);
        S.scT[r0 + 16][2 * h2]     = hsum2(a01);
        S.scT[r0 + 32][2 * h2]     = hsum2(a02);
        S.scT[r0 + 48][2 * h2]     = hsum2(a03);
        S.scT[r0     ][2 * h2 + 1] = hsum2(a10);
        S.scT[r0 + 16][2 * h2 + 1] = hsum2(a11);
        S.scT[r0 + 32][2 * h2 + 1] = hsum2(a12);
        S.scT[r0 + 48][2 * h2 + 1] = hsum2(a13);
        __syncthreads();
    }

    // ---- softmax: 4 warps x 4 columns each (V0 load in flight) ----
    {
        const int w = t >> 5, lane = t & 31;
#pragma unroll
        for (int cc = 0; cc < 4; cc++) {
            const int c = w * 4 + cc;
            const int head = (c >> 1) + ((c & 1) << 3);
            float m = -1e30f;
            for (int i = lane; i < CHUNK; i += 32) m = fmaxf(m, S.scT[i][c]);
#pragma unroll
            for (int off = 16; off > 0; off >>= 1)
                m = fmaxf(m, __shfl_xor_sync(0xffffffffu, m, off));
            float l = 0.f;
            for (int i = lane; i < CHUNK; i += 32) {
                float p = __expf(S.scT[i][c] - m);
                S.scT[i][c] = p;
                l += p;
            }
#pragma unroll
            for (int off = 16; off > 0; off >>= 1)
                l += __shfl_xor_sync(0xffffffffu, l, off);
            if (lane == 0) {
                g_pm[(b * SPLITS + split) * HEADS + head] = m;
                g_pl[(b * SPLITS + split) * HEADS + head] = l;
            }
        }
    }

    // ---- Phase B: O accum, pipelined V subtiles ----
    const int dg = t >> 3;           // 0..15, dims dg*8 .. dg*8+7
    u64 o00 = 0ull, o01 = 0ull, o02 = 0ull, o03 = 0ull;   // head h2
    u64 o10 = 0ull, o11 = 0ull, o12 = 0ull, o13 = 0ull;   // head h2+8
    for (int st = 0; st < 8; st++) {
        if (st < 7) {
            stage_tile(vc, vnew, &S.kt[(st + 1) & 1][0][0], b, sbase + (st + 1) * 64, pos, t);
            asm volatile("cp.async.wait_group 1;");
        } else {
            asm volatile("cp.async.wait_group 0;");
        }
        __syncthreads();

        const float (*vcur)[KTP] = S.kt[st & 1];
#pragma unroll 8
        for (int s = 0; s < 64; s++) {
            float2 p2 = *(const float2*)&S.scT[st * 64 + s][2 * h2];
            u64 pa = pk2(p2.x, p2.x);
            u64 pb = pk2(p2.y, p2.y);
            ulonglong2 v0 = *(const ulonglong2*)&vcur[s][dg * 8];
            ulonglong2 v1 = *(const ulonglong2*)&vcur[s][dg * 8 + 4];
            fma2(o00, v0.x, pa); fma2(o01, v0.y, pa);
            fma2(o02, v1.x, pa); fma2(o03, v1.y, pa);
            fma2(o10, v0.x, pb); fma2(o11, v0.y, pb);
            fma2(o12, v1.x, pb); fma2(o13, v1.y, pb);
        }
        __syncthreads();
    }

    {
        float2 u0 = up2(o00), u1 = up2(o01), u2 = up2(o02), u3 = up2(o03);
        float* dst = g_pout + ((size_t)(b * SPLITS + split) * HEADS + h2) * HDIM + dg * 8;
        float4 r0; r0.x = u0.x; r0.y = u0.y; r0.z = u1.x; r0.w = u1.y;
        float4 r1; r1.x = u2.x; r1.y = u2.y; r1.z = u3.x; r1.w = u3.y;
        ((float4*)dst)[0] = r0;
        ((float4*)dst)[1] = r1;
    }
    {
        float2 u0 = up2(o10), u1 = up2(o11), u2 = up2(o12), u3 = up2(o13);
        float* dst = g_pout + ((size_t)(b * SPLITS + split) * HEADS + h2 + 8) * HDIM + dg * 8;
        float4 r0; r0.x = u0.x; r0.y = u0.y; r0.z = u1.x; r0.w = u1.y;
        float4 r1; r1.x = u2.x; r1.y = u2.y; r1.z = u3.x; r1.w = u3.y;
        ((float4*)dst)[0] = r0;
        ((float4*)dst)[1] = r1;
    }
}

// combine split partials with logsumexp. grid (HEADS, BATCH), 128 threads
__global__ void combine_kernel() {
    const int h = blockIdx.x, b = blockIdx.y, d = threadIdx.x;
    float ms[SPLITS];
    float M = -1e30f;
#pragma unroll
    for (int i = 0; i < SPLITS; i++) {
        ms[i] = g_pm[(b * SPLITS + i) * HEADS + h];
        M = fmaxf(M, ms[i]);
    }
    float Z = 0.f, o = 0.f;
#pragma unroll
    for (int i = 0; i < SPLITS; i++) {
        float e = __expf(ms[i] - M);
        Z += e * g_pl[(b * SPLITS + i) * HEADS + h];
        o += e * g_pout[((size_t)(b * SPLITS + i) * HEADS + h) * HDIM + d];
    }
    g_attn[b * EMB + h * HDIM + d] = o / Z;
}

// =================================================================
// Output projection GEMM (f32x2, register double-buffered loads)
// =================================================================
__global__ void gemm_o_kernel(const float* __restrict__ Wo) {
    __shared__ __align__(16) float xT[64][68];
    __shared__ __align__(16) float ws[64][64];

    const int n0 = blockIdx.x * 64;
    const int ks = blockIdx.y;
    const int t  = threadIdx.x;
    const int nl = t & 63;
    const int mg = t >> 6;
    const int mrow = t >> 2;
    const int q4   = (t & 3) * 16;

    u64 acc2[8];
#pragma unroll
    for (int i = 0; i < 8; i++) acc2[i] = 0ull;

    const int kbase = ks * (EMB / KSPLIT);

    float4 rx[4], rw[4];
    {
        const float4* src = (const float4*)(g_attn + (size_t)mrow * EMB + kbase + q4);
#pragma unroll
        for (int i = 0; i < 4; i++) rx[i] = src[i];
#pragma unroll
        for (int i = 0; i < 4; i++) {
            int f = t + 256 * i; int kr = f >> 4; int nc = (f & 15) * 4;
            rw[i] = *(const float4*)(Wo + (size_t)(kbase + kr) * EMB + n0 + nc);
        }
    }

    for (int kk = 0; kk < EMB / KSPLIT; kk += 64) {
#pragma unroll
        for (int i = 0; i < 4; i++) {
            int kb = q4 + i * 4;
            xT[kb + 0][mrow] = rx[i].x; xT[kb + 1][mrow] = rx[i].y;
            xT[kb + 2][mrow] = rx[i].z; xT[kb + 3][mrow] = rx[i].w;
        }
#pragma unroll
        for (int i = 0; i < 4; i++) {
            int f = t + 256 * i; int kr = f >> 4; int nc = (f & 15) * 4;
            *(float4*)&ws[kr][nc] = rw[i];
        }
        __syncthreads();

        if (kk + 64 < EMB / KSPLIT) {
            const float4* src = (const float4*)(g_attn + (size_t)mrow * EMB + kbase + kk + 64 + q4);
#pragma unroll
            for (int i = 0; i < 4; i++) rx[i] = src[i];
#pragma unroll
            for (int i = 0; i < 4; i++) {
                int f = t + 256 * i; int kr = f >> 4; int nc = (f & 15) * 4;
                rw[i] = *(const float4*)(Wo + (size_t)(kbase + kk + 64 + kr) * EMB + n0 + nc);
            }
        }

#pragma unroll
        for (int k = 0; k < 64; k++) {
            float w = ws[k][nl];
            u64 ww = pk2(w, w);
            const ulonglong2* xr = (const ulonglong2*)&xT[k][mg * 16];
            ulonglong2 p0 = xr[0], p1 = xr[1], p2 = xr[2], p3 = xr[3];
            fma2(acc2[0], p0.x, ww); fma2(acc2[1], p0.y, ww);
            fma2(acc2[2], p1.x, ww); fma2(acc2[3], p1.y, ww);
            fma2(acc2[4], p2.x, ww); fma2(acc2[5], p2.y, ww);
            fma2(acc2[6], p3.x, ww); fma2(acc2[7], p3.y, ww);
        }
        __syncthreads();
    }

#pragma unroll
    for (int i = 0; i < 8; i++) {
        float2 u = up2(acc2[i]);
        int m = mg * 16 + 2 * i;
        g_part_o[((size_t)ks * BATCH + m) * EMB + n0 + nl]     = u.x;
        g_part_o[((size_t)ks * BATCH + m + 1) * EMB + n0 + nl] = u.y;
    }
}

__global__ void reduce_o_kernel(const float* __restrict__ bo, float* __restrict__ out) {
    int i = blockIdx.x * 256 + threadIdx.x;
    if (i >= BATCH * EMB) return;
    int j = i & (EMB - 1);
    float s = 0.f;
#pragma unroll
    for (int ks = 0; ks < KSPLIT; ks++)
        s += g_part_o[(size_t)ks * BATCH * EMB + i];
    out[i] = s + bo[j];
}

// =================================================================
extern "C" void kernel_launch(void* const* d_in, const int* in_sizes, int n_in,
                              void* d_out, int out_size) {
    const float* x   = (const float*)d_in[0];
    const float* kc  = (const float*)d_in[1];
    const float* vc  = (const float*)d_in[2];
    const int*   pos = (const int*)  d_in[3];
    const float* Wq  = (const float*)d_in[4];
    const float* bq  = (const float*)d_in[5];
    const float* Wk  = (const float*)d_in[6];
    const float* bk  = (const float*)d_in[7];
    const float* Wv  = (const float*)d_in[8];
    const float* bv  = (const float*)d_in[9];
    const float* Wo  = (const float*)d_in[10];
    const float* bo  = (const float*)d_in[11];
    float* out = (float*)d_out;

    cudaFuncSetAttribute(attn_kernel, cudaFuncAttributeMaxDynamicSharedMemorySize,
                         (int)sizeof(AttnSmem));

    gemm_qkv_kernel<<<dim3(NQKV / 64, KSPLIT), 256>>>(x, Wq, Wk, Wv);
    reduce_qkv_kernel<<<(BATCH * NQKV + 255) / 256, 256>>>(bq, bk, bv);
    attn_kernel<<<dim3(SPLITS, BATCH), 128, sizeof(AttnSmem)>>>(kc, vc, pos);
    combine_kernel<<<dim3(HEADS, BATCH), 128>>>();
    gemm_o_kernel<<<dim3(EMB / 64, KSPLIT), 256>>>(Wo);
    reduce_o_kernel<<<(BATCH * EMB + 255) / 256, 256>>>(bo, out);
}